// round 16
// baseline (speedup 1.0000x reference)
#include <cuda_runtime.h>
#include <cuda_fp16.h>
#include <cstdint>
#include <math.h>

// Problem constants
#define NN 4096
#define FF 64
#define OO 64
#define KK 5
#define BB 8

// ---------------------------------------------------------------------------
// Scratch layout (float offsets into g_scratch)
// ---------------------------------------------------------------------------
#define OFF_GAMMA   0L          // [B][4096][5] fp32            (163840)
#define OFF_WT      163840L     // fp16 [64o][64f] = W[f,o]     (2048)
#define OFF_W2T     165888L     // fp16 [64o][64f] = W[f,o]^2   (2048)
#define OFF_MU      167936L     // fp16 [5][64] mu              (160)
#define OFF_VA      168096L     // fp16 [5][64] exp(sigma)      (160)
#define OFF_SHIFT_H 168256L     // fp16 [4096][4096]            (8388608)
#define OFF_A2_H    8556864L    // fp16 [4096][4096]            (8388608)
#define OFF_C1T     16945472L   // fp16 [B][128][4096]          (2097152)
#define SCRATCH_TOTAL 19042624L

__device__ float g_scratch[SCRATCH_TOTAL];

// ===========================================================================
// PTX helpers
// ===========================================================================
__device__ __forceinline__ uint32_t smem_to_u32(const void* p) {
    uint32_t a;
    asm("{ .reg .u64 t; cvta.to.shared.u64 t, %1; cvt.u32.u64 %0, t; }"
        : "=r"(a) : "l"(p));
    return a;
}

__device__ __forceinline__ void cp16(uint32_t dst, const void* src) {
    asm volatile("cp.async.cg.shared.global [%0], [%1], 16;"
                 :: "r"(dst), "l"(src) : "memory");
}
#define CP_COMMIT() asm volatile("cp.async.commit_group;" ::: "memory")
#define CP_WAIT1()  asm volatile("cp.async.wait_group 1;" ::: "memory")
#define CP_WAIT0()  asm volatile("cp.async.wait_group 0;" ::: "memory")

__device__ __forceinline__ void ldsm4(uint32_t* f, uint32_t addr) {
    asm volatile("ldmatrix.sync.aligned.m8n8.x4.shared.b16 {%0,%1,%2,%3}, [%4];"
                 : "=r"(f[0]), "=r"(f[1]), "=r"(f[2]), "=r"(f[3]) : "r"(addr));
}

__device__ __forceinline__ void mma_fp16(float* c, const uint32_t* a, const uint32_t* b) {
    asm volatile(
        "mma.sync.aligned.m16n8k16.row.col.f32.f16.f16.f32 "
        "{%0,%1,%2,%3}, {%4,%5,%6,%7}, {%8,%9}, {%0,%1,%2,%3};"
        : "+f"(c[0]), "+f"(c[1]), "+f"(c[2]), "+f"(c[3])
        : "r"(a[0]), "r"(a[1]), "r"(a[2]), "r"(a[3]), "r"(b[0]), "r"(b[1]));
}

__device__ __forceinline__ uint32_t hmul2u(uint32_t a, uint32_t b) {
    __half2 r = __hmul2(*reinterpret_cast<__half2*>(&a),
                        *reinterpret_cast<__half2*>(&b));
    return *reinterpret_cast<uint32_t*>(&r);
}

// SW128 swizzle for 128-byte rows
__device__ __forceinline__ uint32_t swz(int row, int kb) {
    return (uint32_t)(row * 128 + (kb ^ ((row & 7) << 4)));
}
__device__ __forceinline__ uint32_t lda_addr(uint32_t base, int lane, int r0, int kb) {
    int grp = lane >> 3;
    int row = r0 + (lane & 7) + ((grp & 1) << 3);
    int kb2 = kb + ((grp >> 1) << 4);
    return base + swz(row, kb2);
}
__device__ __forceinline__ uint32_t ldb_addr(uint32_t base, int lane, int n0, int kb) {
    int grp = lane >> 3;
    int row = n0 + (lane & 7) + ((grp >> 1) << 3);
    int kb2 = kb + ((grp & 1) << 4);
    return base + swz(row, kb2);
}

// ===========================================================================
// fp32 -> fp16 conversion (both big matrices; y selects matrix)
// ===========================================================================
__global__ void __launch_bounds__(256) convert_h_kernel(
    const float4* __restrict__ s0, uint2* __restrict__ d0,
    const float4* __restrict__ s1, uint2* __restrict__ d1, int n4)
{
    int i = blockIdx.x * 256 + threadIdx.x;
    if (i >= n4) return;
    const float4* src = blockIdx.y ? s1 : s0;
    uint2* dst = blockIdx.y ? d1 : d0;
    float4 v = src[i];
    __half2 h01 = __floats2half2_rn(v.x, v.y);
    __half2 h23 = __floats2half2_rn(v.z, v.w);
    uint2 o;
    o.x = *reinterpret_cast<uint32_t*>(&h01);
    o.y = *reinterpret_cast<uint32_t*>(&h23);
    dst[i] = o;
}

// ===========================================================================
// P0: Wt[o][f]=W[f,o], W2t[o][f]=W[f,o]^2, muh[k][f]=mu, vah[k][f]=exp(sig)
// ===========================================================================
__global__ void prep_consts_kernel(const float* __restrict__ W,
                                   const float* __restrict__ mu,
                                   const float* __restrict__ sigma) {
    int idx = blockIdx.x * 256 + threadIdx.x;
    __half* wt  = (__half*)(g_scratch + OFF_WT);
    __half* w2t = (__half*)(g_scratch + OFF_W2T);
    __half* muh = (__half*)(g_scratch + OFF_MU);
    __half* vah = (__half*)(g_scratch + OFF_VA);
    if (idx < 4096) {
        int o = idx >> 6, f = idx & 63;
        float w = W[f * 64 + o];
        wt[idx]  = __float2half(w);
        w2t[idx] = __float2half(w * w);
    } else if (idx < 4096 + 320) {
        int j = idx - 4096;
        muh[j] = __float2half(mu[j]);
        vah[j] = __float2half(expf(sigma[j]));
    }
}

// ===========================================================================
// P1 fused: per 32-row block: sanitize+transpose features -> C1T fp16,
//           and compute gamma (softmax responsibilities)
// ===========================================================================
__global__ void __launch_bounds__(1024) prep_feat_kernel(
    const float* __restrict__ feat, const float* __restrict__ mu,
    const float* __restrict__ sigma, const float* __restrict__ pi)
{
    __shared__ float mus[KK * 64];
    __shared__ float ivs[KK * 64];
    __shared__ float pis[KK];
    __shared__ __half t[128][34];

    int tx = threadIdx.x, ty = threadIdx.y;
    int tid = ty * 32 + tx;
    if (tid < KK * 64) { mus[tid] = mu[tid]; ivs[tid] = expf(-sigma[tid]); }
    if (tid < KK) pis[tid] = pi[tid];
    __syncthreads();

    int b = blockIdx.y;
    int m0 = blockIdx.x * 32;
    long row = (long)b * NN + m0 + ty;
    float v0 = feat[row * 64 + tx], v1 = feat[row * 64 + tx + 32];
    bool nm0 = isnan(v0), nm1 = isnan(v1);
    float f0 = nm0 ? 0.f : v0;
    float f1 = nm1 ? 0.f : v1;
    t[tx][ty]      = __float2half(f0);
    t[tx + 32][ty] = __float2half(f1);
    t[tx + 64][ty] = __float2half(nm0 ? 1.f : 0.f);
    t[tx + 96][ty] = __float2half(nm1 ? 1.f : 0.f);

    // gamma: warp == row ty, lanes == tx
    float lg[KK];
    #pragma unroll
    for (int k = 0; k < KK; k++) {
        float p = 0.f;
        if (!nm0) { float d = f0 - mus[k * 64 + tx];      p = fmaf(d * d, ivs[k * 64 + tx], p); }
        if (!nm1) { float d = f1 - mus[k * 64 + tx + 32]; p = fmaf(d * d, ivs[k * 64 + tx + 32], p); }
        #pragma unroll
        for (int off = 16; off > 0; off >>= 1) p += __shfl_xor_sync(0xffffffffu, p, off);
        lg[k] = pis[k] - 0.5f * p;
    }
    float mx = lg[0];
    #pragma unroll
    for (int k = 1; k < KK; k++) mx = fmaxf(mx, lg[k]);
    float e[KK], den = 0.f;
    #pragma unroll
    for (int k = 0; k < KK; k++) { e[k] = __expf(lg[k] - mx); den += e[k]; }
    if (tx == 0) {
        float inv = 1.f / den;
        #pragma unroll
        for (int k = 0; k < KK; k++) g_scratch[OFF_GAMMA + row * KK + k] = e[k] * inv;
    }
    __syncthreads();

    // write transposed: 2048 u32 = 128 rows x 16 m-pairs
    uint32_t* dst = (uint32_t*)(g_scratch + OFF_C1T);
    #pragma unroll
    for (int p = 0; p < 2; p++) {
        int i = tid + p * 1024;
        int c = i >> 4, mp = i & 15;
        uint32_t val = *(uint32_t*)&t[c][mp * 2];
        dst[((long)b * 128 + c) * (NN / 2) + (m0 >> 1) + mp] = val;
    }
}

// ===========================================================================
// MEGA kernel v3: 64-row tiles, 256 thr, occ 2, 3-stage pipeline,
//   mainloop warps 2m x 4n (warp tile m32 x n48), single barrier per chunk.
//   cols 0..63 U = shift@featc, 64..127 S = shift@mask, 128..191 T = A2@mask
//   tail: ux=U@Wt^T; per k: dx=(S*mu_k)@Wt^T, dc=(T*var_k)@W2t^T; gamma-mix
// ===========================================================================
#define STG_BYTES 32768         // AS 8K @0 | AA 8K @8192 | B 16K @16384
#define SM_TOT    98304         // 3 stages
// tail layout (valid after mainloop)
#define SM_U    0
#define SM_S    8192
#define SM_T    16384
#define SM_WT   24576
#define SM_W2T  32768
#define SM_G    40960
#define SM_MU   42240
#define SM_VA   42880

__global__ void __launch_bounds__(256, 2)
mega_kernel(const __half* __restrict__ Ash, const __half* __restrict__ Aa2,
            const __half* __restrict__ C1T, float* __restrict__ out)
{
    constexpr int BK = 64;
    constexpr int NC = NN / BK;

    extern __shared__ char smem[];
    uint32_t sbase = smem_to_u32(smem);
    const int tid = threadIdx.x, wid = tid >> 5, lane = tid & 31;
    const int wmM = wid & 1, wnM = wid >> 1;    // mainloop: 2m x 4n, warp tile m32 x n48
    const int m0 = blockIdx.x * 64;
    const int b  = blockIdx.y;

    const __half* Bb = C1T + (long)b * (128L * NN);

    auto load_chunk = [&](int kc) {
        uint32_t st = sbase + (uint32_t)(kc % 3) * STG_BYTES;
        long gc = (long)kc * BK;
        #pragma unroll
        for (int p = 0; p < 2; p++) {
            int idx = tid + p * 256;
            int r = idx >> 3, c16 = idx & 7;
            cp16(st + swz(r, c16 * 16),        Ash + (long)(m0 + r) * NN + gc + c16 * 8);
            cp16(st + 8192 + swz(r, c16 * 16), Aa2 + (long)(m0 + r) * NN + gc + c16 * 8);
        }
        #pragma unroll
        for (int p = 0; p < 4; p++) {
            int idx = tid + p * 256;
            int r = idx >> 3, c16 = idx & 7;
            cp16(st + 16384 + swz(r, c16 * 16), Bb + (long)r * NN + gc + c16 * 8);
        }
        CP_COMMIT();
    };

    float acc[2][6][4] = {};

    load_chunk(0);
    load_chunk(1);

    const bool needS = (wnM < 3);   // shift-A used for cols < 128
    const bool needA = (wnM >= 2);  // A2-A used for cols >= 128

    for (int kc = 0; kc < NC; kc++) {
        if (kc == NC - 1) { CP_WAIT0(); } else { CP_WAIT1(); }
        __syncthreads();
        if (kc + 2 < NC) load_chunk(kc + 2);

        uint32_t st = sbase + (uint32_t)(kc % 3) * STG_BYTES;
        #pragma unroll
        for (int ks = 0; ks < 4; ks++) {
            int kb = ks * 32;
            uint32_t afS[2][4], afA[2][4];
            if (needS) {
                ldsm4(afS[0], lda_addr(st, lane, wmM * 32, kb));
                ldsm4(afS[1], lda_addr(st, lane, wmM * 32 + 16, kb));
            }
            if (needA) {
                ldsm4(afA[0], lda_addr(st + 8192, lane, wmM * 32, kb));
                ldsm4(afA[1], lda_addr(st + 8192, lane, wmM * 32 + 16, kb));
            }
            uint32_t bf[12];
            #pragma unroll
            for (int g = 0; g < 3; g++) {
                int colg = wnM * 48 + g * 16;
                int brow = (colg < 128) ? colg : (colg - 64);
                ldsm4(&bf[g * 4], ldb_addr(st + 16384, lane, brow, kb));
            }
            #pragma unroll
            for (int g = 0; g < 3; g++) {
                bool useS = (wnM * 48 + g * 16) < 128;
                #pragma unroll
                for (int mt = 0; mt < 2; mt++) {
                    #pragma unroll
                    for (int sub = 0; sub < 2; sub++)
                        mma_fp16(acc[mt][g * 2 + sub],
                                 useS ? afS[mt] : afA[mt], &bf[g * 4 + sub * 2]);
                }
            }
        }
    }
    __syncthreads();   // all warps done reading stage smem before spill overwrites

    // --------------------------------------------------------------
    // constants cp.async + fragment spill to SMEM (fp16)
    // --------------------------------------------------------------
    {
        const __half* wtg = (const __half*)(g_scratch + OFF_WT);
        const __half* w2g = (const __half*)(g_scratch + OFF_W2T);
        #pragma unroll
        for (int p = 0; p < 2; p++) {
            int i = tid + p * 256;
            int r = i >> 3, c = i & 7;
            cp16(sbase + SM_WT  + swz(r, c * 16), wtg + (long)i * 8);
            cp16(sbase + SM_W2T + swz(r, c * 16), w2g + (long)i * 8);
        }
        const char* gg = (const char*)(g_scratch + OFF_GAMMA + ((long)b * NN + m0) * KK);
        if (tid < 80) cp16(sbase + SM_G + tid * 16, gg + tid * 16);
        const char* mug = (const char*)(g_scratch + OFF_MU);
        const char* vag = (const char*)(g_scratch + OFF_VA);
        if (tid < 40) {
            cp16(sbase + SM_MU + tid * 16, mug + tid * 16);
            cp16(sbase + SM_VA + tid * 16, vag + tid * 16);
        }
        CP_COMMIT();
    }
    {
        int rl = lane >> 2;
        int q2 = 2 * (lane & 3);
        #pragma unroll
        for (int mt = 0; mt < 2; mt++) {
            int r0 = wmM * 32 + mt * 16 + rl, r1 = r0 + 8;
            #pragma unroll
            for (int j = 0; j < 6; j++) {
                int c = wnM * 48 + j * 8;
                uint32_t base = (c < 64) ? SM_U : (c < 128 ? SM_S : SM_T);
                int cc = (c < 64) ? c : (c < 128 ? c - 64 : c - 128);
                int col2 = (cc + q2) * 2;
                __half2 lo = __floats2half2_rn(acc[mt][j][0], acc[mt][j][1]);
                __half2 hi = __floats2half2_rn(acc[mt][j][2], acc[mt][j][3]);
                *(uint32_t*)(smem + base + r0 * 128 + (col2 ^ ((r0 & 7) << 4))) =
                    *reinterpret_cast<uint32_t*>(&lo);
                *(uint32_t*)(smem + base + r1 * 128 + (col2 ^ ((r1 & 7) << 4))) =
                    *reinterpret_cast<uint32_t*>(&hi);
            }
        }
    }
    CP_WAIT0();
    __syncthreads();

    // --------------------------------------------------------------
    // Tail (own warp layout: 4m x 2n over 64 rows x 64 cols)
    // --------------------------------------------------------------
    const int wm = wid & 3, wn = wid >> 2;
    const int t4 = lane & 3;

    float ux[4][4] = {};
    #pragma unroll
    for (int ks = 0; ks < 4; ks++) {
        int kb = ks * 32;
        uint32_t uf[4];
        ldsm4(uf, lda_addr(sbase + SM_U, lane, wm * 16, kb));
        uint32_t wf[8];
        ldsm4(&wf[0], ldb_addr(sbase + SM_WT, lane, wn * 32, kb));
        ldsm4(&wf[4], ldb_addr(sbase + SM_WT, lane, wn * 32 + 16, kb));
        #pragma unroll
        for (int j = 0; j < 4; j++)
            mma_fp16(ux[j], uf, &wf[j * 2]);
    }

    float oacc[4][4] = {};
    const float* sg = (const float*)(smem + SM_G);

    #pragma unroll 1
    for (int k = 0; k < KK; k++) {
        float dx[4][4] = {};
        float dc[4][4] = {};
        #pragma unroll
        for (int ks = 0; ks < 4; ks++) {
            int kb = ks * 32;
            uint32_t sf[4], tf[4];
            ldsm4(sf, lda_addr(sbase + SM_S, lane, wm * 16, kb));
            ldsm4(tf, lda_addr(sbase + SM_T, lane, wm * 16, kb));
            uint32_t mu0 = *(uint32_t*)(smem + SM_MU + (k * 32 + ks * 8 + t4) * 4);
            uint32_t mu1 = *(uint32_t*)(smem + SM_MU + (k * 32 + ks * 8 + t4 + 4) * 4);
            uint32_t va0 = *(uint32_t*)(smem + SM_VA + (k * 32 + ks * 8 + t4) * 4);
            uint32_t va1 = *(uint32_t*)(smem + SM_VA + (k * 32 + ks * 8 + t4 + 4) * 4);
            sf[0] = hmul2u(sf[0], mu0); sf[1] = hmul2u(sf[1], mu0);
            sf[2] = hmul2u(sf[2], mu1); sf[3] = hmul2u(sf[3], mu1);
            tf[0] = hmul2u(tf[0], va0); tf[1] = hmul2u(tf[1], va0);
            tf[2] = hmul2u(tf[2], va1); tf[3] = hmul2u(tf[3], va1);
            uint32_t wf[8], w2f[8];
            ldsm4(&wf[0],  ldb_addr(sbase + SM_WT,  lane, wn * 32, kb));
            ldsm4(&wf[4],  ldb_addr(sbase + SM_WT,  lane, wn * 32 + 16, kb));
            ldsm4(&w2f[0], ldb_addr(sbase + SM_W2T, lane, wn * 32, kb));
            ldsm4(&w2f[4], ldb_addr(sbase + SM_W2T, lane, wn * 32 + 16, kb));
            #pragma unroll
            for (int j = 0; j < 4; j++) {
                mma_fp16(dx[j], sf, &wf[j * 2]);
                mma_fp16(dc[j], tf, &w2f[j * 2]);
            }
        }
        int rl0 = wm * 16 + (lane >> 2);
        float g0 = sg[rl0 * KK + k];
        float g1 = sg[(rl0 + 8) * KK + k];
        #pragma unroll
        for (int j = 0; j < 4; j++) {
            #pragma unroll
            for (int v = 0; v < 4; v++) {
                float mean = ux[j][v] + dx[j][v];
                float var  = dc[j][v];
                float sd = sqrtf(fmaxf(var, 0.f));
                float ex;
                if (sd > 0.f) {
                    float zz = mean / sd;
                    ex = mean * normcdff(zz)
                       + sd * __expf(-0.5f * zz * zz) * 0.3989422804014327f;
                } else {
                    ex = fmaxf(mean, 0.f);
                }
                float g = (v < 2) ? g0 : g1;
                oacc[j][v] = fmaf(g, ex, oacc[j][v]);
            }
        }
    }

    float* ob = out + ((long)b * NN + m0) * 64;
    {
        int r = wm * 16 + (lane >> 2);
        int q2 = 2 * (lane & 3);
        #pragma unroll
        for (int j = 0; j < 4; j++) {
            int c = wn * 32 + j * 8 + q2;
            *(float2*)(ob + (long)r * 64 + c)       = make_float2(oacc[j][0], oacc[j][1]);
            *(float2*)(ob + (long)(r + 8) * 64 + c) = make_float2(oacc[j][2], oacc[j][3]);
        }
    }
}

// ===========================================================================
// Launch
// ===========================================================================
extern "C" void kernel_launch(void* const* d_in, const int* in_sizes, int n_in,
                              void* d_out, int out_size) {
    const float* shift = (const float*)d_in[0];
    const float* A2    = (const float*)d_in[1];
    const float* feat  = (const float*)d_in[2];
    const float* W     = (const float*)d_in[3];
    const float* pi    = (const float*)d_in[4];
    const float* mu    = (const float*)d_in[5];
    const float* sigma = (const float*)d_in[6];
    float* out = (float*)d_out;

    float* scr = nullptr;
    cudaGetSymbolAddress((void**)&scr, g_scratch);

    __half* shift_h = (__half*)(scr + OFF_SHIFT_H);
    __half* a2_h    = (__half*)(scr + OFF_A2_H);
    __half* c1t     = (__half*)(scr + OFF_C1T);

    const int n4 = NN * NN / 4;
    convert_h_kernel<<<dim3((n4 + 255) / 256, 2), 256>>>(
        (const float4*)shift, (uint2*)shift_h,
        (const float4*)A2, (uint2*)a2_h, n4);

    prep_consts_kernel<<<(4096 + 320 + 255) / 256, 256>>>(W, mu, sigma);
    prep_feat_kernel<<<dim3(NN / 32, BB), dim3(32, 32)>>>(feat, mu, sigma, pi);

    cudaFuncSetAttribute(mega_kernel,
                         cudaFuncAttributeMaxDynamicSharedMemorySize, SM_TOT);
    mega_kernel<<<dim3(NN / 64, BB), 256, SM_TOT>>>(shift_h, a2_h, c1t, out);
}

// round 17
// speedup vs baseline: 1.1021x; 1.1021x over previous
#include <cuda_runtime.h>
#include <cuda_fp16.h>
#include <cstdint>
#include <math.h>

// Problem constants
#define NN 4096
#define FF 64
#define OO 64
#define KK 5
#define BB 8

// ---------------------------------------------------------------------------
// Scratch layout (float offsets into g_scratch)
// ---------------------------------------------------------------------------
#define OFF_GAMMA   0L          // [B][4096][5] fp32            (163840)
#define OFF_WT      163840L     // fp16 [64o][64f] = W[f,o]     (2048)
#define OFF_W2T     165888L     // fp16 [64o][64f] = W[f,o]^2   (2048)
#define OFF_MU      167936L     // fp16 [5][64] mu              (160)
#define OFF_VA      168096L     // fp16 [5][64] exp(sigma)      (160)
#define OFF_SHIFT_H 168256L     // fp16 [4096][4096]            (8388608)
#define OFF_A2_H    8556864L    // fp16 [4096][4096]            (8388608)
#define OFF_C1T     16945472L   // fp16 [B][128][4096]          (2097152)
#define SCRATCH_TOTAL 19042624L

__device__ float g_scratch[SCRATCH_TOTAL];

// ===========================================================================
// PTX helpers
// ===========================================================================
__device__ __forceinline__ uint32_t smem_to_u32(const void* p) {
    uint32_t a;
    asm("{ .reg .u64 t; cvta.to.shared.u64 t, %1; cvt.u32.u64 %0, t; }"
        : "=r"(a) : "l"(p));
    return a;
}

__device__ __forceinline__ void cp16(uint32_t dst, const void* src) {
    asm volatile("cp.async.cg.shared.global [%0], [%1], 16;"
                 :: "r"(dst), "l"(src) : "memory");
}
#define CP_COMMIT() asm volatile("cp.async.commit_group;" ::: "memory")
#define CP_WAIT1()  asm volatile("cp.async.wait_group 1;" ::: "memory")
#define CP_WAIT0()  asm volatile("cp.async.wait_group 0;" ::: "memory")

__device__ __forceinline__ void ldsm4(uint32_t* f, uint32_t addr) {
    asm volatile("ldmatrix.sync.aligned.m8n8.x4.shared.b16 {%0,%1,%2,%3}, [%4];"
                 : "=r"(f[0]), "=r"(f[1]), "=r"(f[2]), "=r"(f[3]) : "r"(addr));
}

__device__ __forceinline__ void mma_fp16(float* c, const uint32_t* a, const uint32_t* b) {
    asm volatile(
        "mma.sync.aligned.m16n8k16.row.col.f32.f16.f16.f32 "
        "{%0,%1,%2,%3}, {%4,%5,%6,%7}, {%8,%9}, {%0,%1,%2,%3};"
        : "+f"(c[0]), "+f"(c[1]), "+f"(c[2]), "+f"(c[3])
        : "r"(a[0]), "r"(a[1]), "r"(a[2]), "r"(a[3]), "r"(b[0]), "r"(b[1]));
}

__device__ __forceinline__ uint32_t hmul2u(uint32_t a, uint32_t b) {
    __half2 r = __hmul2(*reinterpret_cast<__half2*>(&a),
                        *reinterpret_cast<__half2*>(&b));
    return *reinterpret_cast<uint32_t*>(&r);
}

// SW128 swizzle for 128-byte rows
__device__ __forceinline__ uint32_t swz(int row, int kb) {
    return (uint32_t)(row * 128 + (kb ^ ((row & 7) << 4)));
}
__device__ __forceinline__ uint32_t lda_addr(uint32_t base, int lane, int r0, int kb) {
    int grp = lane >> 3;
    int row = r0 + (lane & 7) + ((grp & 1) << 3);
    int kb2 = kb + ((grp >> 1) << 4);
    return base + swz(row, kb2);
}
__device__ __forceinline__ uint32_t ldb_addr(uint32_t base, int lane, int n0, int kb) {
    int grp = lane >> 3;
    int row = n0 + (lane & 7) + ((grp >> 1) << 3);
    int kb2 = kb + ((grp & 1) << 4);
    return base + swz(row, kb2);
}

// ===========================================================================
// fp32 -> fp16 conversion (both big matrices; y selects matrix)
// ===========================================================================
__global__ void __launch_bounds__(256) convert_h_kernel(
    const float4* __restrict__ s0, uint2* __restrict__ d0,
    const float4* __restrict__ s1, uint2* __restrict__ d1, int n4)
{
    int i = blockIdx.x * 256 + threadIdx.x;
    if (i >= n4) return;
    const float4* src = blockIdx.y ? s1 : s0;
    uint2* dst = blockIdx.y ? d1 : d0;
    float4 v = src[i];
    __half2 h01 = __floats2half2_rn(v.x, v.y);
    __half2 h23 = __floats2half2_rn(v.z, v.w);
    uint2 o;
    o.x = *reinterpret_cast<uint32_t*>(&h01);
    o.y = *reinterpret_cast<uint32_t*>(&h23);
    dst[i] = o;
}

// ===========================================================================
// P0: Wt[o][f]=W[f,o], W2t[o][f]=W[f,o]^2, muh[k][f]=mu, vah[k][f]=exp(sig)
// ===========================================================================
__global__ void prep_consts_kernel(const float* __restrict__ W,
                                   const float* __restrict__ mu,
                                   const float* __restrict__ sigma) {
    int idx = blockIdx.x * 256 + threadIdx.x;
    __half* wt  = (__half*)(g_scratch + OFF_WT);
    __half* w2t = (__half*)(g_scratch + OFF_W2T);
    __half* muh = (__half*)(g_scratch + OFF_MU);
    __half* vah = (__half*)(g_scratch + OFF_VA);
    if (idx < 4096) {
        int o = idx >> 6, f = idx & 63;
        float w = W[f * 64 + o];
        wt[idx]  = __float2half(w);
        w2t[idx] = __float2half(w * w);
    } else if (idx < 4096 + 320) {
        int j = idx - 4096;
        muh[j] = __float2half(mu[j]);
        vah[j] = __float2half(expf(sigma[j]));
    }
}

// ===========================================================================
// P1 fused: per 32-row block: sanitize+transpose features -> C1T fp16,
//           and compute gamma (softmax responsibilities)
// ===========================================================================
__global__ void __launch_bounds__(1024) prep_feat_kernel(
    const float* __restrict__ feat, const float* __restrict__ mu,
    const float* __restrict__ sigma, const float* __restrict__ pi)
{
    __shared__ float mus[KK * 64];
    __shared__ float ivs[KK * 64];
    __shared__ float pis[KK];
    __shared__ __half t[128][34];

    int tx = threadIdx.x, ty = threadIdx.y;
    int tid = ty * 32 + tx;
    if (tid < KK * 64) { mus[tid] = mu[tid]; ivs[tid] = expf(-sigma[tid]); }
    if (tid < KK) pis[tid] = pi[tid];
    __syncthreads();

    int b = blockIdx.y;
    int m0 = blockIdx.x * 32;
    long row = (long)b * NN + m0 + ty;
    float v0 = feat[row * 64 + tx], v1 = feat[row * 64 + tx + 32];
    bool nm0 = isnan(v0), nm1 = isnan(v1);
    float f0 = nm0 ? 0.f : v0;
    float f1 = nm1 ? 0.f : v1;
    t[tx][ty]      = __float2half(f0);
    t[tx + 32][ty] = __float2half(f1);
    t[tx + 64][ty] = __float2half(nm0 ? 1.f : 0.f);
    t[tx + 96][ty] = __float2half(nm1 ? 1.f : 0.f);

    // gamma: warp == row ty, lanes == tx
    float lg[KK];
    #pragma unroll
    for (int k = 0; k < KK; k++) {
        float p = 0.f;
        if (!nm0) { float d = f0 - mus[k * 64 + tx];      p = fmaf(d * d, ivs[k * 64 + tx], p); }
        if (!nm1) { float d = f1 - mus[k * 64 + tx + 32]; p = fmaf(d * d, ivs[k * 64 + tx + 32], p); }
        #pragma unroll
        for (int off = 16; off > 0; off >>= 1) p += __shfl_xor_sync(0xffffffffu, p, off);
        lg[k] = pis[k] - 0.5f * p;
    }
    float mx = lg[0];
    #pragma unroll
    for (int k = 1; k < KK; k++) mx = fmaxf(mx, lg[k]);
    float e[KK], den = 0.f;
    #pragma unroll
    for (int k = 0; k < KK; k++) { e[k] = __expf(lg[k] - mx); den += e[k]; }
    if (tx == 0) {
        float inv = 1.f / den;
        #pragma unroll
        for (int k = 0; k < KK; k++) g_scratch[OFF_GAMMA + row * KK + k] = e[k] * inv;
    }
    __syncthreads();

    // write transposed: 2048 u32 = 128 rows x 16 m-pairs
    uint32_t* dst = (uint32_t*)(g_scratch + OFF_C1T);
    #pragma unroll
    for (int p = 0; p < 2; p++) {
        int i = tid + p * 1024;
        int c = i >> 4, mp = i & 15;
        uint32_t val = *(uint32_t*)&t[c][mp * 2];
        dst[((long)b * 128 + c) * (NN / 2) + (m0 >> 1) + mp] = val;
    }
}

// ===========================================================================
// MEGA kernel v4: R14 mainloop (4m x 2n warp-uniform branch) + ONE barrier
//   per k-chunk. 64-row tiles, 256 thr, occ 2, 3-stage pipeline.
//   cols 0..63 U = shift@featc, 64..127 S = shift@mask, 128..191 T = A2@mask
//   tail: ux=U@Wt^T; per k: dx=(S*mu_k)@Wt^T, dc=(T*var_k)@W2t^T; gamma-mix
// ===========================================================================
#define STG_BYTES 32768         // AS 8K @0 | AA 8K @8192 | B 16K @16384
#define SM_TOT    98304         // 3 stages
// tail layout (valid after mainloop)
#define SM_U    0
#define SM_S    8192
#define SM_T    16384
#define SM_WT   24576
#define SM_W2T  32768
#define SM_G    40960
#define SM_MU   42240
#define SM_VA   42880

__global__ void __launch_bounds__(256, 2)
mega_kernel(const __half* __restrict__ Ash, const __half* __restrict__ Aa2,
            const __half* __restrict__ C1T, float* __restrict__ out)
{
    constexpr int BK = 64;
    constexpr int NC = NN / BK;

    extern __shared__ char smem[];
    uint32_t sbase = smem_to_u32(smem);
    const int tid = threadIdx.x, wid = tid >> 5, lane = tid & 31;
    const int wm = wid & 3, wn = wid >> 2;      // mainloop + tail: 4m x 2n
    const int m0 = blockIdx.x * 64;
    const int b  = blockIdx.y;

    const __half* Bb = C1T + (long)b * (128L * NN);

    auto load_chunk = [&](int kc) {
        uint32_t st = sbase + (uint32_t)(kc % 3) * STG_BYTES;
        long gc = (long)kc * BK;
        #pragma unroll
        for (int p = 0; p < 2; p++) {
            int idx = tid + p * 256;
            int r = idx >> 3, c16 = idx & 7;
            cp16(st + swz(r, c16 * 16),        Ash + (long)(m0 + r) * NN + gc + c16 * 8);
            cp16(st + 8192 + swz(r, c16 * 16), Aa2 + (long)(m0 + r) * NN + gc + c16 * 8);
        }
        #pragma unroll
        for (int p = 0; p < 4; p++) {
            int idx = tid + p * 256;
            int r = idx >> 3, c16 = idx & 7;
            cp16(st + 16384 + swz(r, c16 * 16), Bb + (long)r * NN + gc + c16 * 8);
        }
        CP_COMMIT();
    };

    // acc[j]: wn==0 -> cols j*8 of 0..95 (U + S-lo) with shift-A rows wm*16
    //         wn==1 -> j<4: S-hi cols 96..127 (shift-A); j>=4: T cols 128..191 (A2-A)
    float acc[12][4] = {};

    load_chunk(0);
    load_chunk(1);

    for (int kc = 0; kc < NC; kc++) {
        if (kc == NC - 1) { CP_WAIT0(); } else { CP_WAIT1(); }
        __syncthreads();            // stage kc ready AND stage (kc-1)%3 free
        if (kc + 2 < NC) load_chunk(kc + 2);

        uint32_t st = sbase + (uint32_t)(kc % 3) * STG_BYTES;
        #pragma unroll
        for (int ks = 0; ks < 4; ks++) {
            int kb = ks * 32;
            uint32_t af[4];
            ldsm4(af, lda_addr(st, lane, wm * 16, kb));          // shift A rows
            if (wn == 0) {
                uint32_t bf[24];
                #pragma unroll
                for (int p = 0; p < 6; p++)
                    ldsm4(&bf[p * 4], ldb_addr(st + 16384, lane, p * 16, kb));
                #pragma unroll
                for (int j = 0; j < 12; j++)
                    mma_fp16(acc[j], af, &bf[j * 2]);
            } else {
                uint32_t af2[4];
                ldsm4(af2, lda_addr(st + 8192, lane, wm * 16, kb));  // A2 rows
                uint32_t bf[16];                                      // B rows 64..127
                #pragma unroll
                for (int p = 0; p < 4; p++)
                    ldsm4(&bf[p * 4], ldb_addr(st + 16384, lane, 64 + p * 16, kb));
                // tiles 0..3 => cols 96..127 (S hi) : shift A, B rows 96..127
                #pragma unroll
                for (int j = 0; j < 4; j++)
                    mma_fp16(acc[j], af, &bf[(4 + j) * 2]);
                // tiles 4..11 => cols 128..191 (T) : A2, B rows 64..127
                #pragma unroll
                for (int j = 4; j < 12; j++)
                    mma_fp16(acc[j], af2, &bf[(j - 4) * 2]);
            }
        }
    }
    __syncthreads();   // all warps done reading stage smem before spill overwrites

    // --------------------------------------------------------------
    // constants cp.async + fragment spill to SMEM (fp16)
    // --------------------------------------------------------------
    {
        const __half* wtg = (const __half*)(g_scratch + OFF_WT);
        const __half* w2g = (const __half*)(g_scratch + OFF_W2T);
        #pragma unroll
        for (int p = 0; p < 2; p++) {
            int i = tid + p * 256;
            int r = i >> 3, c = i & 7;
            cp16(sbase + SM_WT  + swz(r, c * 16), wtg + (long)i * 8);
            cp16(sbase + SM_W2T + swz(r, c * 16), w2g + (long)i * 8);
        }
        const char* gg = (const char*)(g_scratch + OFF_GAMMA + ((long)b * NN + m0) * KK);
        if (tid < 80) cp16(sbase + SM_G + tid * 16, gg + tid * 16);
        const char* mug = (const char*)(g_scratch + OFF_MU);
        const char* vag = (const char*)(g_scratch + OFF_VA);
        if (tid < 40) {
            cp16(sbase + SM_MU + tid * 16, mug + tid * 16);
            cp16(sbase + SM_VA + tid * 16, vag + tid * 16);
        }
        CP_COMMIT();
    }
    {
        int rl = lane >> 2;
        int q2 = 2 * (lane & 3);
        int r0 = wm * 16 + rl, r1 = r0 + 8;
        #pragma unroll
        for (int j = 0; j < 12; j++) {
            int c = wn * 96 + j * 8;
            uint32_t base = (c < 64) ? SM_U : (c < 128 ? SM_S : SM_T);
            int cc = (c < 64) ? c : (c < 128 ? c - 64 : c - 128);
            int col2 = (cc + q2) * 2;
            __half2 lo = __floats2half2_rn(acc[j][0], acc[j][1]);
            __half2 hi = __floats2half2_rn(acc[j][2], acc[j][3]);
            *(uint32_t*)(smem + base + r0 * 128 + (col2 ^ ((r0 & 7) << 4))) =
                *reinterpret_cast<uint32_t*>(&lo);
            *(uint32_t*)(smem + base + r1 * 128 + (col2 ^ ((r1 & 7) << 4))) =
                *reinterpret_cast<uint32_t*>(&hi);
        }
    }
    CP_WAIT0();
    __syncthreads();

    // --------------------------------------------------------------
    // Tail (4m x 2n over 64 rows x 64 cols)
    // --------------------------------------------------------------
    const int t4 = lane & 3;

    float ux[4][4] = {};
    #pragma unroll
    for (int ks = 0; ks < 4; ks++) {
        int kb = ks * 32;
        uint32_t uf[4];
        ldsm4(uf, lda_addr(sbase + SM_U, lane, wm * 16, kb));
        uint32_t wf[8];
        ldsm4(&wf[0], ldb_addr(sbase + SM_WT, lane, wn * 32, kb));
        ldsm4(&wf[4], ldb_addr(sbase + SM_WT, lane, wn * 32 + 16, kb));
        #pragma unroll
        for (int j = 0; j < 4; j++)
            mma_fp16(ux[j], uf, &wf[j * 2]);
    }

    float oacc[4][4] = {};
    const float* sg = (const float*)(smem + SM_G);

    #pragma unroll 1
    for (int k = 0; k < KK; k++) {
        float dx[4][4] = {};
        float dc[4][4] = {};
        #pragma unroll
        for (int ks = 0; ks < 4; ks++) {
            int kb = ks * 32;
            uint32_t sf[4], tf[4];
            ldsm4(sf, lda_addr(sbase + SM_S, lane, wm * 16, kb));
            ldsm4(tf, lda_addr(sbase + SM_T, lane, wm * 16, kb));
            uint32_t mu0 = *(uint32_t*)(smem + SM_MU + (k * 32 + ks * 8 + t4) * 4);
            uint32_t mu1 = *(uint32_t*)(smem + SM_MU + (k * 32 + ks * 8 + t4 + 4) * 4);
            uint32_t va0 = *(uint32_t*)(smem + SM_VA + (k * 32 + ks * 8 + t4) * 4);
            uint32_t va1 = *(uint32_t*)(smem + SM_VA + (k * 32 + ks * 8 + t4 + 4) * 4);
            sf[0] = hmul2u(sf[0], mu0); sf[1] = hmul2u(sf[1], mu0);
            sf[2] = hmul2u(sf[2], mu1); sf[3] = hmul2u(sf[3], mu1);
            tf[0] = hmul2u(tf[0], va0); tf[1] = hmul2u(tf[1], va0);
            tf[2] = hmul2u(tf[2], va1); tf[3] = hmul2u(tf[3], va1);
            uint32_t wf[8], w2f[8];
            ldsm4(&wf[0],  ldb_addr(sbase + SM_WT,  lane, wn * 32, kb));
            ldsm4(&wf[4],  ldb_addr(sbase + SM_WT,  lane, wn * 32 + 16, kb));
            ldsm4(&w2f[0], ldb_addr(sbase + SM_W2T, lane, wn * 32, kb));
            ldsm4(&w2f[4], ldb_addr(sbase + SM_W2T, lane, wn * 32 + 16, kb));
            #pragma unroll
            for (int j = 0; j < 4; j++) {
                mma_fp16(dx[j], sf, &wf[j * 2]);
                mma_fp16(dc[j], tf, &w2f[j * 2]);
            }
        }
        int rl0 = wm * 16 + (lane >> 2);
        float g0 = sg[rl0 * KK + k];
        float g1 = sg[(rl0 + 8) * KK + k];
        #pragma unroll
        for (int j = 0; j < 4; j++) {
            #pragma unroll
            for (int v = 0; v < 4; v++) {
                float mean = ux[j][v] + dx[j][v];
                float var  = dc[j][v];
                float sd = sqrtf(fmaxf(var, 0.f));
                float ex;
                if (sd > 0.f) {
                    float zz = mean / sd;
                    ex = mean * normcdff(zz)
                       + sd * __expf(-0.5f * zz * zz) * 0.3989422804014327f;
                } else {
                    ex = fmaxf(mean, 0.f);
                }
                float g = (v < 2) ? g0 : g1;
                oacc[j][v] = fmaf(g, ex, oacc[j][v]);
            }
        }
    }

    float* ob = out + ((long)b * NN + m0) * 64;
    {
        int r = wm * 16 + (lane >> 2);
        int q2 = 2 * (lane & 3);
        #pragma unroll
        for (int j = 0; j < 4; j++) {
            int c = wn * 32 + j * 8 + q2;
            *(float2*)(ob + (long)r * 64 + c)       = make_float2(oacc[j][0], oacc[j][1]);
            *(float2*)(ob + (long)(r + 8) * 64 + c) = make_float2(oacc[j][2], oacc[j][3]);
        }
    }
}

// ===========================================================================
// Launch
// ===========================================================================
extern "C" void kernel_launch(void* const* d_in, const int* in_sizes, int n_in,
                              void* d_out, int out_size) {
    const float* shift = (const float*)d_in[0];
    const float* A2    = (const float*)d_in[1];
    const float* feat  = (const float*)d_in[2];
    const float* W     = (const float*)d_in[3];
    const float* pi    = (const float*)d_in[4];
    const float* mu    = (const float*)d_in[5];
    const float* sigma = (const float*)d_in[6];
    float* out = (float*)d_out;

    float* scr = nullptr;
    cudaGetSymbolAddress((void**)&scr, g_scratch);

    __half* shift_h = (__half*)(scr + OFF_SHIFT_H);
    __half* a2_h    = (__half*)(scr + OFF_A2_H);
    __half* c1t     = (__half*)(scr + OFF_C1T);

    const int n4 = NN * NN / 4;
    convert_h_kernel<<<dim3((n4 + 255) / 256, 2), 256>>>(
        (const float4*)shift, (uint2*)shift_h,
        (const float4*)A2, (uint2*)a2_h, n4);

    prep_consts_kernel<<<(4096 + 320 + 255) / 256, 256>>>(W, mu, sigma);
    prep_feat_kernel<<<dim3(NN / 32, BB), dim3(32, 32)>>>(feat, mu, sigma, pi);

    cudaFuncSetAttribute(mega_kernel,
                         cudaFuncAttributeMaxDynamicSharedMemorySize, SM_TOT);
    mega_kernel<<<dim3(NN / 64, BB), 256, SM_TOT>>>(shift_h, a2_h, c1t, out);
}